// round 3
// baseline (speedup 1.0000x reference)
#include <cuda_runtime.h>
#include <math.h>

#define BATCH 16384
#define G 64
#define NH0 256
#define NH1 512
#define NH2 256
#define NF 4096   // G*G

// Expected packed-output element offsets (fp32):
//   flux  [B,64,64] at 0
//   q     [B,64]    at B*NF
//   press [B]       at B*NF + B*G
//   loss  [1]       at B*NF + B*G + B
#define OFF_Q    ((size_t)BATCH * NF)
#define OFF_P    (OFF_Q + (size_t)BATCH * G)
#define OFF_LOSS (OFF_P + (size_t)BATCH)
#define FULL_OUT (OFF_LOSS + 1)

// ---------------- scratch (static device globals: allocation-guard safe) ----
__device__ float g_h0[(size_t)BATCH * NH0];
__device__ float g_t1[(size_t)BATCH * NH1];
__device__ float g_t2[(size_t)BATCH * NH2];
__device__ float g_gs[BATCH];
__device__ float g_cc[BATCH];

// ---------------- helpers ---------------------------------------------------
__device__ __forceinline__ float geluf(float x) {
    return 0.5f * x * (1.0f + erff(x * 0.70710678118654752440f));
}

__device__ __forceinline__ float block_reduce_sum(float v, float* red, int n) {
    int t = threadIdx.x;
    red[t] = v;
    __syncthreads();
    for (int s = n >> 1; s > 0; s >>= 1) {
        if (t < s) red[t] += red[t + s];
        __syncthreads();
    }
    float r = red[0];
    __syncthreads();
    return r;
}

// ---------------- K1: encoder Linear(8->256) + GELU + LayerNorm -------------
__global__ __launch_bounds__(256) void k_encoder(
    const float* __restrict__ x, const float* __restrict__ W,
    const float* __restrict__ b, const float* __restrict__ g,
    const float* __restrict__ be)
{
    __shared__ float xs[8];
    __shared__ float red[256];
    int row = blockIdx.x, t = threadIdx.x;
    if (t < 8) xs[t] = x[row * 8 + t];
    __syncthreads();
    float acc = b[t];
#pragma unroll
    for (int k = 0; k < 8; k++) acc = fmaf(xs[k], W[k * NH0 + t], acc);
    float v = geluf(acc);
    float mu  = block_reduce_sum(v, red, 256) * (1.0f / NH0);
    float d   = v - mu;
    float var = block_reduce_sum(d * d, red, 256) * (1.0f / NH0);
    g_h0[(size_t)row * NH0 + t] = d * rsqrtf(var + 1e-5f) * g[t] + be[t];
}

// ---------------- LayerNorm over rows of length N (in place) ----------------
template <int N>
__global__ __launch_bounds__(N) void k_layernorm(float* __restrict__ data,
                            const float* __restrict__ g,
                            const float* __restrict__ be)
{
    __shared__ float red[N];
    int row = blockIdx.x, t = threadIdx.x;
    float v = data[(size_t)row * N + t];
    float mu  = block_reduce_sum(v, red, N) * (1.0f / N);
    float d   = v - mu;
    float var = block_reduce_sum(d * d, red, N) * (1.0f / N);
    data[(size_t)row * N + t] = d * rsqrtf(var + 1e-5f) * g[t] + be[t];
}

// ---------------- tiled SGEMM (64x64x16, 4x4 micro) + bias + GELU -----------
template <int K>
__global__ __launch_bounds__(256) void k_gemm_gelu(
    const float* __restrict__ A, const float* __restrict__ W,
    const float* __restrict__ bias, float* __restrict__ C, int N)
{
    __shared__ float As[16][64];
    __shared__ float Bs[16][64];
    int tid = threadIdx.x;
    int tx = tid & 15, ty = tid >> 4;
    int m0 = blockIdx.y * 64, n0 = blockIdx.x * 64;
    float acc[4][4] = {};
    int lar = tid >> 2, lac = (tid & 3) * 4;   // A loader: row 0..63, col group
    int lbr = tid >> 4, lbc = (tid & 15) * 4;  // W loader: row 0..15
    const float* Ag = A + (size_t)(m0 + lar) * K + lac;
    const float* Wg = W + (size_t)lbr * N + n0 + lbc;

    for (int k0 = 0; k0 < K; k0 += 16) {
        float4 av = *(const float4*)(Ag + k0);
        As[lac + 0][lar] = av.x; As[lac + 1][lar] = av.y;
        As[lac + 2][lar] = av.z; As[lac + 3][lar] = av.w;
        float4 bv = *(const float4*)(Wg + (size_t)k0 * N);
        *(float4*)&Bs[lbr][lbc] = bv;
        __syncthreads();
#pragma unroll
        for (int kk = 0; kk < 16; kk++) {
            float a[4], bb[4];
            *(float4*)a  = *(const float4*)&As[kk][ty * 4];
            *(float4*)bb = *(const float4*)&Bs[kk][tx * 4];
#pragma unroll
            for (int i = 0; i < 4; i++)
#pragma unroll
                for (int j = 0; j < 4; j++)
                    acc[i][j] = fmaf(a[i], bb[j], acc[i][j]);
        }
        __syncthreads();
    }
#pragma unroll
    for (int i = 0; i < 4; i++) {
        int m = m0 + ty * 4 + i;
#pragma unroll
        for (int j = 0; j < 4; j++) {
            int n = n0 + tx * 4 + j;
            C[(size_t)m * N + n] = geluf(acc[i][j] + bias[n]);
        }
    }
}

// ---------------- K4: flux GEMM (N-tile == one grid row) + cummax epilogue --
// flux = sigmoid(tanh(cummax(z)))  (monotone fns commute with cummax)
template <int K>
__global__ __launch_bounds__(256) void k_final(
    const float* __restrict__ A, const float* __restrict__ W,
    const float* __restrict__ bias, float* __restrict__ flux,
    size_t out_elems)
{
    __shared__ float As[16][64];
    __shared__ float Bs[16][64];
    __shared__ float zs[64][65];
    int tid = threadIdx.x;
    int tx = tid & 15, ty = tid >> 4;
    int m0 = blockIdx.y * 64, n0 = blockIdx.x * 64;   // n0 = grid-row*64
    float acc[4][4] = {};
    int lar = tid >> 2, lac = (tid & 3) * 4;
    int lbr = tid >> 4, lbc = (tid & 15) * 4;
    const float* Ag = A + (size_t)(m0 + lar) * K + lac;
    const float* Wg = W + (size_t)lbr * NF + n0 + lbc;

    for (int k0 = 0; k0 < K; k0 += 16) {
        float4 av = *(const float4*)(Ag + k0);
        As[lac + 0][lar] = av.x; As[lac + 1][lar] = av.y;
        As[lac + 2][lar] = av.z; As[lac + 3][lar] = av.w;
        float4 bv = *(const float4*)(Wg + (size_t)k0 * NF);
        *(float4*)&Bs[lbr][lbc] = bv;
        __syncthreads();
#pragma unroll
        for (int kk = 0; kk < 16; kk++) {
            float a[4], bb[4];
            *(float4*)a  = *(const float4*)&As[kk][ty * 4];
            *(float4*)bb = *(const float4*)&Bs[kk][tx * 4];
#pragma unroll
            for (int i = 0; i < 4; i++)
#pragma unroll
                for (int j = 0; j < 4; j++)
                    acc[i][j] = fmaf(a[i], bb[j], acc[i][j]);
        }
        __syncthreads();
    }
#pragma unroll
    for (int i = 0; i < 4; i++)
#pragma unroll
        for (int j = 0; j < 4; j++)
            zs[ty * 4 + i][tx * 4 + j] = acc[i][j] + bias[n0 + tx * 4 + j];
    __syncthreads();
    if (tid < 64) {  // inclusive running-max along the 64-col grid row
        float run = -3.402823466e38f;
        for (int j = 0; j < 64; j++) {
            run = fmaxf(run, zs[tid][j]);
            zs[tid][j] = run;
        }
    }
    __syncthreads();
    int jc = tid & 63, mb = tid >> 6;
#pragma unroll
    for (int r = 0; r < 16; r++) {
        int m = mb * 16 + r;
        float z = zs[m][jc];
        float f = 1.0f / (1.0f + expf(-tanhf(z)));
        size_t idx = (size_t)(m0 + m) * NF + n0 + jc;
        if (idx < out_elems) flux[idx] = f;   // OOB guard
    }
}

// ---------------- K5: per-sample physics (Laplacian, sums, q, pressure) -----
__global__ __launch_bounds__(256) void k_physics(
    const float* __restrict__ flux, const float* __restrict__ x,
    float* __restrict__ out, size_t out_elems)
{
    __shared__ float fs[64][65];
    __shared__ float red[256];
    int b = blockIdx.x, t = threadIdx.x;
    const float* fb = flux + (size_t)b * NF;
    float lsum = 0.0f;
#pragma unroll
    for (int i = 0; i < 16; i++) {
        int idx = i * 256 + t;
        float v = fb[idx];
        fs[idx >> 6][idx & 63] = v;
        lsum += v;
    }
    __syncthreads();
    float S  = block_reduce_sum(lsum, red, 256);
    float x0 = x[(size_t)b * 8];
    float lq = 0.0f;
    for (int p = t; p < 62 * 62; p += 256) {
        int i = p / 62 + 1, j = p % 62 + 1;
        float lap = fs[i + 1][j] + fs[i - 1][j] + fs[i][j + 1] + fs[i][j - 1]
                    - 4.0f * fs[i][j];
        float d = lap - x0;
        lq = fmaf(d, d, lq);
    }
    float LQ = block_reduce_sum(lq, red, 256);
    if (t == 0) {
        g_gs[b] = LQ + 252.0f * x0 * x0;   // 252 boundary cells: lap=0 -> x0^2
        float dc = x0 - S;
        g_cc[b] = dc * dc;
        size_t pi = OFF_P + (size_t)b;
        if (pi < out_elems) out[pi] = expf(-2.0f * S * (1.0f / NF));
    }
    if (t < 64) {
        size_t qi = OFF_Q + (size_t)b * G + t;
        if (qi < out_elems) out[qi] = 0.8f + (float)t * (2.7f / 63.0f);
    }
}

// ---------------- K6: scalar loss -------------------------------------------
__global__ __launch_bounds__(1024) void k_loss(const float* __restrict__ pw,
                                               float* __restrict__ out,
                                               size_t out_elems)
{
    __shared__ float r1[1024];
    __shared__ float r2[1024];
    int t = threadIdx.x;
    float sg = 0.0f, sc = 0.0f;
    for (int i = t; i < BATCH; i += 1024) { sg += g_gs[i]; sc += g_cc[i]; }
    r1[t] = sg; r2[t] = sc;
    __syncthreads();
    for (int s = 512; s > 0; s >>= 1) {
        if (t < s) { r1[t] += r1[t + s]; r2[t] += r2[t + s]; }
        __syncthreads();
    }
    if (t == 0 && OFF_LOSS < out_elems) {
        float gs_res = r1[0] * (1.0f / ((float)BATCH * (float)NF));
        float cc     = r2[0] * (1.0f / (float)BATCH);
        float stab   = fmaxf(0.0f, 1.1f - 0.8f);  // q min == linspace start
        out[OFF_LOSS] = pw[0] * gs_res + pw[1] * cc + pw[2] * stab;
    }
}

// Thin device-global-access wrappers for GEMM in/out (no cudaGetSymbolAddress:
// kernels reference the globals directly via these launch shims).
__global__ __launch_bounds__(256) void k_gemm1(
    const float* __restrict__ W, const float* __restrict__ bias)
{
    // delegates by inlining k_gemm_gelu body is complex; instead we launch
    // k_gemm_gelu with pointers obtained in device code — not possible from
    // host. So: use small pointer-fetch kernels writing into a device slot.
    (void)W; (void)bias;
}

// Device-side pointer table so host never needs cudaGetSymbolAddress.
__device__ float* g_ptrs[3];
__global__ void k_init_ptrs() {
    g_ptrs[0] = g_h0; g_ptrs[1] = g_t1; g_ptrs[2] = g_t2;
}

// GEMM wrappers that read scratch pointers from the device table.
template <int K>
__global__ __launch_bounds__(256) void k_gemm_gelu_ind(
    int src, const float* __restrict__ W,
    const float* __restrict__ bias, int dst, int N)
{
    const float* A = g_ptrs[src];
    float* C = g_ptrs[dst];
    __shared__ float As[16][64];
    __shared__ float Bs[16][64];
    int tid = threadIdx.x;
    int tx = tid & 15, ty = tid >> 4;
    int m0 = blockIdx.y * 64, n0 = blockIdx.x * 64;
    float acc[4][4] = {};
    int lar = tid >> 2, lac = (tid & 3) * 4;
    int lbr = tid >> 4, lbc = (tid & 15) * 4;
    const float* Ag = A + (size_t)(m0 + lar) * K + lac;
    const float* Wg = W + (size_t)lbr * N + n0 + lbc;

    for (int k0 = 0; k0 < K; k0 += 16) {
        float4 av = *(const float4*)(Ag + k0);
        As[lac + 0][lar] = av.x; As[lac + 1][lar] = av.y;
        As[lac + 2][lar] = av.z; As[lac + 3][lar] = av.w;
        float4 bv = *(const float4*)(Wg + (size_t)k0 * N);
        *(float4*)&Bs[lbr][lbc] = bv;
        __syncthreads();
#pragma unroll
        for (int kk = 0; kk < 16; kk++) {
            float a[4], bb[4];
            *(float4*)a  = *(const float4*)&As[kk][ty * 4];
            *(float4*)bb = *(const float4*)&Bs[kk][tx * 4];
#pragma unroll
            for (int i = 0; i < 4; i++)
#pragma unroll
                for (int j = 0; j < 4; j++)
                    acc[i][j] = fmaf(a[i], bb[j], acc[i][j]);
        }
        __syncthreads();
    }
#pragma unroll
    for (int i = 0; i < 4; i++) {
        int m = m0 + ty * 4 + i;
#pragma unroll
        for (int j = 0; j < 4; j++) {
            int n = n0 + tx * 4 + j;
            C[(size_t)m * N + n] = geluf(acc[i][j] + bias[n]);
        }
    }
}

template <int N>
__global__ __launch_bounds__(N) void k_layernorm_ind(
    int buf, const float* __restrict__ g, const float* __restrict__ be)
{
    float* data = g_ptrs[buf];
    __shared__ float red[N];
    int row = blockIdx.x, t = threadIdx.x;
    float v = data[(size_t)row * N + t];
    float mu  = block_reduce_sum(v, red, N) * (1.0f / N);
    float d   = v - mu;
    float var = block_reduce_sum(d * d, red, N) * (1.0f / N);
    data[(size_t)row * N + t] = d * rsqrtf(var + 1e-5f) * g[t] + be[t];
}

template <int K>
__global__ __launch_bounds__(256) void k_final_ind(
    int src, const float* __restrict__ W,
    const float* __restrict__ bias, float* __restrict__ flux,
    size_t out_elems)
{
    const float* A = g_ptrs[src];
    __shared__ float As[16][64];
    __shared__ float Bs[16][64];
    __shared__ float zs[64][65];
    int tid = threadIdx.x;
    int tx = tid & 15, ty = tid >> 4;
    int m0 = blockIdx.y * 64, n0 = blockIdx.x * 64;
    float acc[4][4] = {};
    int lar = tid >> 2, lac = (tid & 3) * 4;
    int lbr = tid >> 4, lbc = (tid & 15) * 4;
    const float* Ag = A + (size_t)(m0 + lar) * K + lac;
    const float* Wg = W + (size_t)lbr * NF + n0 + lbc;

    for (int k0 = 0; k0 < K; k0 += 16) {
        float4 av = *(const float4*)(Ag + k0);
        As[lac + 0][lar] = av.x; As[lac + 1][lar] = av.y;
        As[lac + 2][lar] = av.z; As[lac + 3][lar] = av.w;
        float4 bv = *(const float4*)(Wg + (size_t)k0 * NF);
        *(float4*)&Bs[lbr][lbc] = bv;
        __syncthreads();
#pragma unroll
        for (int kk = 0; kk < 16; kk++) {
            float a[4], bb[4];
            *(float4*)a  = *(const float4*)&As[kk][ty * 4];
            *(float4*)bb = *(const float4*)&Bs[kk][tx * 4];
#pragma unroll
            for (int i = 0; i < 4; i++)
#pragma unroll
                for (int j = 0; j < 4; j++)
                    acc[i][j] = fmaf(a[i], bb[j], acc[i][j]);
        }
        __syncthreads();
    }
#pragma unroll
    for (int i = 0; i < 4; i++)
#pragma unroll
        for (int j = 0; j < 4; j++)
            zs[ty * 4 + i][tx * 4 + j] = acc[i][j] + bias[n0 + tx * 4 + j];
    __syncthreads();
    if (tid < 64) {
        float run = -3.402823466e38f;
        for (int j = 0; j < 64; j++) {
            run = fmaxf(run, zs[tid][j]);
            zs[tid][j] = run;
        }
    }
    __syncthreads();
    int jc = tid & 63, mb = tid >> 6;
#pragma unroll
    for (int r = 0; r < 16; r++) {
        int m = mb * 16 + r;
        float z = zs[m][jc];
        float f = 1.0f / (1.0f + expf(-tanhf(z)));
        size_t idx = (size_t)(m0 + m) * NF + n0 + jc;
        if (idx < out_elems) flux[idx] = f;
    }
}

// ---------------- launch -----------------------------------------------------
extern "C" void kernel_launch(void* const* d_in, const int* in_sizes, int n_in,
                              void* d_out, int out_size)
{
    (void)in_sizes; (void)n_in;
    const float* x     = (const float*)d_in[0];
    const float* Wenc  = (const float*)d_in[1];
    const float* benc  = (const float*)d_in[2];
    const float* genc  = (const float*)d_in[3];
    const float* beenc = (const float*)d_in[4];
    const float* W1    = (const float*)d_in[5];
    const float* b1    = (const float*)d_in[6];
    const float* g1    = (const float*)d_in[7];
    const float* be1   = (const float*)d_in[8];
    const float* W2    = (const float*)d_in[9];
    const float* b2    = (const float*)d_in[10];
    const float* g2    = (const float*)d_in[11];
    const float* be2   = (const float*)d_in[12];
    const float* Wf    = (const float*)d_in[13];
    const float* bf    = (const float*)d_in[14];
    const float* pw    = (const float*)d_in[15];

    float* out = (float*)d_out;
    size_t out_elems = (size_t)out_size;

    k_init_ptrs<<<1, 1>>>();
    k_encoder<<<BATCH, 256>>>(x, Wenc, benc, genc, beenc);
    k_gemm_gelu_ind<NH0><<<dim3(NH1 / 64, BATCH / 64), 256>>>(0, W1, b1, 1, NH1);
    k_layernorm_ind<NH1><<<BATCH, NH1>>>(1, g1, be1);
    k_gemm_gelu_ind<NH1><<<dim3(NH2 / 64, BATCH / 64), 256>>>(1, W2, b2, 2, NH2);
    k_layernorm_ind<NH2><<<BATCH, NH2>>>(2, g2, be2);
    k_final_ind<NH2><<<dim3(NF / 64, BATCH / 64), 256>>>(2, Wf, bf, out, out_elems);
    k_physics<<<BATCH, 256>>>(out, x, out, out_elems);
    k_loss<<<1, 1024>>>(pw, out, out_elems);
}

// round 4
// speedup vs baseline: 1.4017x; 1.4017x over previous
#include <cuda_runtime.h>
#include <math.h>
#include <stdint.h>

#define BATCH 16384
#define G 64
#define NH0 256
#define NH1 512
#define NH2 256
#define NF 4096   // G*G

// packed fp32 output: flux [B,64,64] | q [B,64] | pressure [B] | loss [1]
#define OFF_Q    ((size_t)BATCH * NF)
#define OFF_P    (OFF_Q + (size_t)BATCH * G)
#define OFF_LOSS (OFF_P + (size_t)BATCH)

// ---------------- scratch ----------------------------------------------------
__device__ float g_h0[(size_t)BATCH * NH0];
__device__ float g_t1[(size_t)BATCH * NH1];
__device__ float g_t2[(size_t)BATCH * NH2];
__device__ float g_gs[BATCH];
__device__ float g_cc[BATCH];

// device pointer table (host never calls cudaGetSymbolAddress)
__device__ float* g_ptrs[3];
__global__ void k_init_ptrs() {
    g_ptrs[0] = g_h0; g_ptrs[1] = g_t1; g_ptrs[2] = g_t2;
}

// ---------------- helpers ----------------------------------------------------
__device__ __forceinline__ float geluf(float x) {
    return 0.5f * x * (1.0f + erff(x * 0.70710678118654752440f));
}

__device__ __forceinline__ float block_reduce_sum(float v, float* red, int n) {
    int t = threadIdx.x;
    red[t] = v;
    __syncthreads();
    for (int s = n >> 1; s > 0; s >>= 1) {
        if (t < s) red[t] += red[t + s];
        __syncthreads();
    }
    float r = red[0];
    __syncthreads();
    return r;
}

__device__ __forceinline__ uint32_t f2tf32(float f) {
    uint32_t u;
    asm("cvt.rna.tf32.f32 %0, %1;" : "=r"(u) : "f"(f));
    return u;
}

__device__ __forceinline__ void mma_tf32(float d[4],
    uint32_t a0, uint32_t a1, uint32_t a2, uint32_t a3,
    uint32_t b0, uint32_t b1)
{
    asm volatile(
        "mma.sync.aligned.m16n8k8.row.col.f32.tf32.tf32.f32 "
        "{%0,%1,%2,%3}, {%4,%5,%6,%7}, {%8,%9}, {%0,%1,%2,%3};\n"
        : "+f"(d[0]), "+f"(d[1]), "+f"(d[2]), "+f"(d[3])
        : "r"(a0), "r"(a1), "r"(a2), "r"(a3), "r"(b0), "r"(b1));
}

// ---------------- K1: encoder Linear(8->256) + GELU + LayerNorm --------------
__global__ __launch_bounds__(256) void k_encoder(
    const float* __restrict__ x, const float* __restrict__ W,
    const float* __restrict__ b, const float* __restrict__ g,
    const float* __restrict__ be)
{
    __shared__ float xs[8];
    __shared__ float red[256];
    int row = blockIdx.x, t = threadIdx.x;
    if (t < 8) xs[t] = x[row * 8 + t];
    __syncthreads();
    float acc = b[t];
#pragma unroll
    for (int k = 0; k < 8; k++) acc = fmaf(xs[k], W[k * NH0 + t], acc);
    float v = geluf(acc);
    float mu  = block_reduce_sum(v, red, 256) * (1.0f / NH0);
    float d   = v - mu;
    float var = block_reduce_sum(d * d, red, 256) * (1.0f / NH0);
    g_h0[(size_t)row * NH0 + t] = d * rsqrtf(var + 1e-5f) * g[t] + be[t];
}

// ---------------- LayerNorm (indirect buffer) --------------------------------
template <int N>
__global__ __launch_bounds__(N) void k_layernorm_ind(
    int buf, const float* __restrict__ g, const float* __restrict__ be)
{
    float* data = g_ptrs[buf];
    __shared__ float red[N];
    int row = blockIdx.x, t = threadIdx.x;
    float v = data[(size_t)row * N + t];
    float mu  = block_reduce_sum(v, red, N) * (1.0f / N);
    float d   = v - mu;
    float var = block_reduce_sum(d * d, red, N) * (1.0f / N);
    data[(size_t)row * N + t] = d * rsqrtf(var + 1e-5f) * g[t] + be[t];
}

// ---------------- hidden GEMM (fp32 FFMA, 64x64x16, 4x4 micro) + GELU --------
template <int K>
__global__ __launch_bounds__(256) void k_gemm_gelu_ind(
    int src, const float* __restrict__ W,
    const float* __restrict__ bias, int dst, int N)
{
    const float* A = g_ptrs[src];
    float* C = g_ptrs[dst];
    __shared__ float As[16][64];
    __shared__ float Bs[16][64];
    int tid = threadIdx.x;
    int tx = tid & 15, ty = tid >> 4;
    int m0 = blockIdx.y * 64, n0 = blockIdx.x * 64;
    float acc[4][4] = {};
    int lar = tid >> 2, lac = (tid & 3) * 4;
    int lbr = tid >> 4, lbc = (tid & 15) * 4;
    const float* Ag = A + (size_t)(m0 + lar) * K + lac;
    const float* Wg = W + (size_t)lbr * N + n0 + lbc;

    for (int k0 = 0; k0 < K; k0 += 16) {
        float4 av = *(const float4*)(Ag + k0);
        As[lac + 0][lar] = av.x; As[lac + 1][lar] = av.y;
        As[lac + 2][lar] = av.z; As[lac + 3][lar] = av.w;
        float4 bv = *(const float4*)(Wg + (size_t)k0 * N);
        *(float4*)&Bs[lbr][lbc] = bv;
        __syncthreads();
#pragma unroll
        for (int kk = 0; kk < 16; kk++) {
            float a[4], bb[4];
            *(float4*)a  = *(const float4*)&As[kk][ty * 4];
            *(float4*)bb = *(const float4*)&Bs[kk][tx * 4];
#pragma unroll
            for (int i = 0; i < 4; i++)
#pragma unroll
                for (int j = 0; j < 4; j++)
                    acc[i][j] = fmaf(a[i], bb[j], acc[i][j]);
        }
        __syncthreads();
    }
#pragma unroll
    for (int i = 0; i < 4; i++) {
        int m = m0 + ty * 4 + i;
#pragma unroll
        for (int j = 0; j < 4; j++) {
            int n = n0 + tx * 4 + j;
            C[(size_t)m * N + n] = geluf(acc[i][j] + bias[n]);
        }
    }
}

// ---------------- K4: flux GEMM via tf32 mma.sync + cummax epilogue ----------
// block tile 128(M) x 64(N), K=256 in chunks of 32. 8 warps: 4(m) x 2(n),
// each warp 32x32 = 2 m16 tiles x 4 n8 tiles.
// flux = sigmoid(tanh(cummax(z)))  (monotone fns commute with cummax)
#define AS_STRIDE 40   // 32 + 8 pad: A-frag loads conflict-free (8*g + tg)
#define BS_STRIDE 72   // 64 + 8 pad: B-frag loads conflict-free (8*tg... distinct)

__global__ __launch_bounds__(256) void k_final_mma(
    int src, const float* __restrict__ W,
    const float* __restrict__ bias, float* __restrict__ flux,
    size_t out_elems)
{
    const float* A = g_ptrs[src];
    __shared__ union {
        struct {
            float As[128][AS_STRIDE];   // [m][k] chunk
            float Bs[32][BS_STRIDE];    // [k][n] chunk
        } mm;
        float zs[128][65];
    } sm;

    int tid  = threadIdx.x;
    int wid  = tid >> 5;
    int lane = tid & 31;
    int group = lane >> 2;      // 0..7
    int tg    = lane & 3;       // 0..3
    int wm = (wid >> 1) * 32;   // warp m-strip base (0,32,64,96)
    int wn = (wid & 1) * 32;    // warp n-strip base (0,32)

    int m0 = blockIdx.y * 128;
    int n0 = blockIdx.x * 64;   // n0 = grid-row * 64

    float d[2][4][4] = {};      // [m-tile][n-tile][c-regs]

    const float* Ag = A + (size_t)m0 * NH2;
    const float* Wg = W + n0;

#pragma unroll 1
    for (int k0 = 0; k0 < NH2; k0 += 32) {
        // stage A chunk: 128 x 32 floats = 1024 float4, 4 per thread
#pragma unroll
        for (int it = 0; it < 4; it++) {
            int i = tid + 256 * it;
            int r = i >> 3, c4 = (i & 7) * 4;
            float4 v = *(const float4*)(Ag + (size_t)r * NH2 + k0 + c4);
            sm.mm.As[r][c4 + 0] = v.x; sm.mm.As[r][c4 + 1] = v.y;
            sm.mm.As[r][c4 + 2] = v.z; sm.mm.As[r][c4 + 3] = v.w;
        }
        // stage B chunk: 32 x 64 floats = 512 float4, 2 per thread
#pragma unroll
        for (int it = 0; it < 2; it++) {
            int i = tid + 256 * it;
            int kk = i >> 4, c4 = (i & 15) * 4;
            float4 v = *(const float4*)(Wg + (size_t)(k0 + kk) * NF + c4);
            sm.mm.Bs[kk][c4 + 0] = v.x; sm.mm.Bs[kk][c4 + 1] = v.y;
            sm.mm.Bs[kk][c4 + 2] = v.z; sm.mm.Bs[kk][c4 + 3] = v.w;
        }
        __syncthreads();

#pragma unroll
        for (int ks = 0; ks < 32; ks += 8) {
            // A fragments: 2 m16 tiles
            uint32_t afr[2][4];
#pragma unroll
            for (int mt = 0; mt < 2; mt++) {
                int mb = wm + mt * 16;
                afr[mt][0] = f2tf32(sm.mm.As[mb + group    ][ks + tg    ]);
                afr[mt][1] = f2tf32(sm.mm.As[mb + group + 8][ks + tg    ]);
                afr[mt][2] = f2tf32(sm.mm.As[mb + group    ][ks + tg + 4]);
                afr[mt][3] = f2tf32(sm.mm.As[mb + group + 8][ks + tg + 4]);
            }
            // B fragments: 4 n8 tiles
            uint32_t bfr[4][2];
#pragma unroll
            for (int nt = 0; nt < 4; nt++) {
                int nb = wn + nt * 8;
                bfr[nt][0] = f2tf32(sm.mm.Bs[ks + tg    ][nb + group]);
                bfr[nt][1] = f2tf32(sm.mm.Bs[ks + tg + 4][nb + group]);
            }
#pragma unroll
            for (int mt = 0; mt < 2; mt++)
#pragma unroll
                for (int nt = 0; nt < 4; nt++)
                    mma_tf32(d[mt][nt],
                             afr[mt][0], afr[mt][1], afr[mt][2], afr[mt][3],
                             bfr[nt][0], bfr[nt][1]);
        }
        __syncthreads();
    }

    // write z (+bias) into zs (union reuse of staging smem)
#pragma unroll
    for (int mt = 0; mt < 2; mt++) {
#pragma unroll
        for (int nt = 0; nt < 4; nt++) {
            int rb = wm + mt * 16 + group;
            int cb = wn + nt * 8 + 2 * tg;
            float bz0 = bias[n0 + cb], bz1 = bias[n0 + cb + 1];
            sm.zs[rb    ][cb    ] = d[mt][nt][0] + bz0;
            sm.zs[rb    ][cb + 1] = d[mt][nt][1] + bz1;
            sm.zs[rb + 8][cb    ] = d[mt][nt][2] + bz0;
            sm.zs[rb + 8][cb + 1] = d[mt][nt][3] + bz1;
        }
    }
    __syncthreads();

    // inclusive running max along 64-col grid row (thread per row)
    if (tid < 128) {
        float run = -3.402823466e38f;
#pragma unroll 4
        for (int j = 0; j < 64; j++) {
            run = fmaxf(run, sm.zs[tid][j]);
            sm.zs[tid][j] = run;
        }
    }
    __syncthreads();

    // flux = sigmoid(tanh(z)) and store
#pragma unroll
    for (int i = 0; i < 32; i++) {
        int idx = tid + 256 * i;
        int r = idx >> 6, c = idx & 63;
        float z = sm.zs[r][c];
        float e2z = __expf(2.0f * z);
        float th  = (e2z - 1.0f) / (e2z + 1.0f);
        float f   = 1.0f / (1.0f + __expf(-th));
        size_t gi = (size_t)(m0 + r) * NF + n0 + c;
        if (gi < out_elems) flux[gi] = f;
    }
}

// ---------------- K5: per-sample physics -------------------------------------
__global__ __launch_bounds__(256) void k_physics(
    const float* __restrict__ flux, const float* __restrict__ x,
    float* __restrict__ out, size_t out_elems)
{
    __shared__ float fs[64][65];
    __shared__ float red[256];
    int b = blockIdx.x, t = threadIdx.x;
    const float* fb = flux + (size_t)b * NF;
    float lsum = 0.0f;
#pragma unroll
    for (int i = 0; i < 16; i++) {
        int idx = i * 256 + t;
        float v = fb[idx];
        fs[idx >> 6][idx & 63] = v;
        lsum += v;
    }
    __syncthreads();
    float S  = block_reduce_sum(lsum, red, 256);
    float x0 = x[(size_t)b * 8];
    float lq = 0.0f;
    for (int p = t; p < 62 * 62; p += 256) {
        int i = p / 62 + 1, j = p % 62 + 1;
        float lap = fs[i + 1][j] + fs[i - 1][j] + fs[i][j + 1] + fs[i][j - 1]
                    - 4.0f * fs[i][j];
        float dd = lap - x0;
        lq = fmaf(dd, dd, lq);
    }
    float LQ = block_reduce_sum(lq, red, 256);
    if (t == 0) {
        g_gs[b] = LQ + 252.0f * x0 * x0;   // boundary cells: lap=0 -> (0-x0)^2
        float dc = x0 - S;
        g_cc[b] = dc * dc;
        size_t pi = OFF_P + (size_t)b;
        if (pi < out_elems) out[pi] = expf(-2.0f * S * (1.0f / NF));
    }
    if (t < 64) {
        size_t qi = OFF_Q + (size_t)b * G + t;
        if (qi < out_elems) out[qi] = 0.8f + (float)t * (2.7f / 63.0f);
    }
}

// ---------------- K6: scalar loss --------------------------------------------
__global__ __launch_bounds__(1024) void k_loss(const float* __restrict__ pw,
                                               float* __restrict__ out,
                                               size_t out_elems)
{
    __shared__ float r1[1024];
    __shared__ float r2[1024];
    int t = threadIdx.x;
    float sg = 0.0f, sc = 0.0f;
    for (int i = t; i < BATCH; i += 1024) { sg += g_gs[i]; sc += g_cc[i]; }
    r1[t] = sg; r2[t] = sc;
    __syncthreads();
    for (int s = 512; s > 0; s >>= 1) {
        if (t < s) { r1[t] += r1[t + s]; r2[t] += r2[t + s]; }
        __syncthreads();
    }
    if (t == 0 && OFF_LOSS < out_elems) {
        float gs_res = r1[0] * (1.0f / ((float)BATCH * (float)NF));
        float cc     = r2[0] * (1.0f / (float)BATCH);
        float stab   = fmaxf(0.0f, 1.1f - 0.8f);  // q min == linspace start
        out[OFF_LOSS] = pw[0] * gs_res + pw[1] * cc + pw[2] * stab;
    }
}

// ---------------- launch -----------------------------------------------------
extern "C" void kernel_launch(void* const* d_in, const int* in_sizes, int n_in,
                              void* d_out, int out_size)
{
    (void)in_sizes; (void)n_in;
    const float* x     = (const float*)d_in[0];
    const float* Wenc  = (const float*)d_in[1];
    const float* benc  = (const float*)d_in[2];
    const float* genc  = (const float*)d_in[3];
    const float* beenc = (const float*)d_in[4];
    const float* W1    = (const float*)d_in[5];
    const float* b1    = (const float*)d_in[6];
    const float* g1    = (const float*)d_in[7];
    const float* be1   = (const float*)d_in[8];
    const float* W2    = (const float*)d_in[9];
    const float* b2    = (const float*)d_in[10];
    const float* g2    = (const float*)d_in[11];
    const float* be2   = (const float*)d_in[12];
    const float* Wf    = (const float*)d_in[13];
    const float* bf    = (const float*)d_in[14];
    const float* pw    = (const float*)d_in[15];

    float* out = (float*)d_out;
    size_t out_elems = (size_t)out_size;

    k_init_ptrs<<<1, 1>>>();
    k_encoder<<<BATCH, 256>>>(x, Wenc, benc, genc, beenc);
    k_gemm_gelu_ind<NH0><<<dim3(NH1 / 64, BATCH / 64), 256>>>(0, W1, b1, 1, NH1);
    k_layernorm_ind<NH1><<<BATCH, NH1>>>(1, g1, be1);
    k_gemm_gelu_ind<NH1><<<dim3(NH2 / 64, BATCH / 64), 256>>>(1, W2, b2, 2, NH2);
    k_layernorm_ind<NH2><<<BATCH, NH2>>>(2, g2, be2);
    k_final_mma<<<dim3(NF / 64, BATCH / 128), 256>>>(2, Wf, bf, out, out_elems);
    k_physics<<<BATCH, 256>>>(out, x, out, out_elems);
    k_loss<<<1, 1024>>>(pw, out, out_elems);
}

// round 5
// speedup vs baseline: 1.8287x; 1.3046x over previous
#include <cuda_runtime.h>
#include <math.h>
#include <stdint.h>

#define BATCH 16384
#define G 64
#define NH0 256
#define NH1 512
#define NH2 256
#define NF 4096   // G*G

// packed fp32 output: flux [B,64,64] | q [B,64] | pressure [B] | loss [1]
#define OFF_Q    ((size_t)BATCH * NF)
#define OFF_P    (OFF_Q + (size_t)BATCH * G)
#define OFF_LOSS (OFF_P + (size_t)BATCH)

// ---------------- scratch ----------------------------------------------------
__device__ float g_h0[(size_t)BATCH * NH0];
__device__ float g_t1[(size_t)BATCH * NH1];
__device__ float g_t2[(size_t)BATCH * NH2];
__device__ float g_gs[BATCH];
__device__ float g_cc[BATCH];

__device__ float* g_ptrs[3];
__global__ void k_init_ptrs() {
    g_ptrs[0] = g_h0; g_ptrs[1] = g_t1; g_ptrs[2] = g_t2;
}

// ---------------- helpers ----------------------------------------------------
__device__ __forceinline__ float geluf(float x) {
    return 0.5f * x * (1.0f + erff(x * 0.70710678118654752440f));
}

__device__ __forceinline__ float block_reduce_sum(float v, float* red, int n) {
    int t = threadIdx.x;
    red[t] = v;
    __syncthreads();
    for (int s = n >> 1; s > 0; s >>= 1) {
        if (t < s) red[t] += red[t + s];
        __syncthreads();
    }
    float r = red[0];
    __syncthreads();
    return r;
}

__device__ __forceinline__ uint32_t f2tf32(float f) {
    uint32_t u;
    asm("cvt.rna.tf32.f32 %0, %1;" : "=r"(u) : "f"(f));
    return u;
}

__device__ __forceinline__ void mma_tf32(float d[4],
    uint32_t a0, uint32_t a1, uint32_t a2, uint32_t a3,
    uint32_t b0, uint32_t b1)
{
    asm volatile(
        "mma.sync.aligned.m16n8k8.row.col.f32.tf32.tf32.f32 "
        "{%0,%1,%2,%3}, {%4,%5,%6,%7}, {%8,%9}, {%0,%1,%2,%3};\n"
        : "+f"(d[0]), "+f"(d[1]), "+f"(d[2]), "+f"(d[3])
        : "r"(a0), "r"(a1), "r"(a2), "r"(a3), "r"(b0), "r"(b1));
}

// ---------------- shared tf32 GEMM mainloop ----------------------------------
// block tile 128(M) x 64(N), 8 warps 4(m)x2(n), warp 32x32, K chunked by 32.
// smem holds PRE-CONVERTED tf32 (uint32): inner loop is pure LDS+MMA.
#define AS_STRIDE 36   // (36*g mod 32 = 4g) + tg covers banks 0..31: conflict-free
#define BS_STRIDE 72   // (8*tg + group): conflict-free

struct MMASmem {
    uint32_t As[128][AS_STRIDE];   // [m][k] chunk, tf32 bits
    uint32_t Bs[32][BS_STRIDE];    // [k][n] chunk, tf32 bits
};

template <int K, int NSTR>
__device__ __forceinline__ void mma_tiles(
    const float* __restrict__ A, const float* __restrict__ W,
    int m0, int n0, MMASmem& sm, float (&d)[2][4][4],
    int wm, int wn, int group, int tg, int tid)
{
    const float* Ag = A + (size_t)m0 * K;
    const float* Wg = W + n0;
#pragma unroll 1
    for (int k0 = 0; k0 < K; k0 += 32) {
        // stage A chunk 128x32 (4 float4/thread), converting to tf32
#pragma unroll
        for (int it = 0; it < 4; it++) {
            int i = tid + 256 * it;
            int r = i >> 3, c4 = (i & 7) * 4;
            float4 v = *(const float4*)(Ag + (size_t)r * K + k0 + c4);
            uint4 u = make_uint4(f2tf32(v.x), f2tf32(v.y), f2tf32(v.z), f2tf32(v.w));
            *(uint4*)&sm.As[r][c4] = u;
        }
        // stage B chunk 32x64 (2 float4/thread)
#pragma unroll
        for (int it = 0; it < 2; it++) {
            int i = tid + 256 * it;
            int kk = i >> 4, c4 = (i & 15) * 4;
            float4 v = *(const float4*)(Wg + (size_t)(k0 + kk) * NSTR + c4);
            uint4 u = make_uint4(f2tf32(v.x), f2tf32(v.y), f2tf32(v.z), f2tf32(v.w));
            *(uint4*)&sm.Bs[kk][c4] = u;
        }
        __syncthreads();

#pragma unroll
        for (int ks = 0; ks < 32; ks += 8) {
            uint32_t afr[2][4];
#pragma unroll
            for (int mt = 0; mt < 2; mt++) {
                int mb = wm + mt * 16;
                afr[mt][0] = sm.As[mb + group    ][ks + tg    ];
                afr[mt][1] = sm.As[mb + group + 8][ks + tg    ];
                afr[mt][2] = sm.As[mb + group    ][ks + tg + 4];
                afr[mt][3] = sm.As[mb + group + 8][ks + tg + 4];
            }
            uint32_t bfr[4][2];
#pragma unroll
            for (int nt = 0; nt < 4; nt++) {
                int nb = wn + nt * 8;
                bfr[nt][0] = sm.Bs[ks + tg    ][nb + group];
                bfr[nt][1] = sm.Bs[ks + tg + 4][nb + group];
            }
#pragma unroll
            for (int mt = 0; mt < 2; mt++)
#pragma unroll
                for (int nt = 0; nt < 4; nt++)
                    mma_tf32(d[mt][nt],
                             afr[mt][0], afr[mt][1], afr[mt][2], afr[mt][3],
                             bfr[nt][0], bfr[nt][1]);
        }
        __syncthreads();
    }
}

// ---------------- hidden GEMM: tf32 mma + bias + GELU ------------------------
template <int K, int NOUT>
__global__ __launch_bounds__(256) void k_gemm_tf32(
    int src, const float* __restrict__ W,
    const float* __restrict__ bias, int dst)
{
    const float* A = g_ptrs[src];
    float* C = g_ptrs[dst];
    __shared__ MMASmem sm;
    int tid = threadIdx.x, wid = tid >> 5, lane = tid & 31;
    int group = lane >> 2, tg = lane & 3;
    int wm = (wid >> 1) * 32, wn = (wid & 1) * 32;
    int m0 = blockIdx.y * 128, n0 = blockIdx.x * 64;
    float d[2][4][4] = {};
    mma_tiles<K, NOUT>(A, W, m0, n0, sm, d, wm, wn, group, tg, tid);
#pragma unroll
    for (int mt = 0; mt < 2; mt++) {
#pragma unroll
        for (int nt = 0; nt < 4; nt++) {
            int r0 = m0 + wm + mt * 16 + group;
            int c  = n0 + wn + nt * 8 + 2 * tg;
            float b0 = bias[c], b1 = bias[c + 1];
            float2 o0 = make_float2(geluf(d[mt][nt][0] + b0), geluf(d[mt][nt][1] + b1));
            float2 o1 = make_float2(geluf(d[mt][nt][2] + b0), geluf(d[mt][nt][3] + b1));
            *(float2*)&C[(size_t)r0 * NOUT + c]       = o0;
            *(float2*)&C[(size_t)(r0 + 8) * NOUT + c] = o1;
        }
    }
}

// ---------------- warp-per-row LayerNorm (shuffle reduce, no smem) -----------
template <int N>
__global__ __launch_bounds__(256) void k_layernorm_warp(
    int buf, const float* __restrict__ g, const float* __restrict__ be)
{
    float* data = g_ptrs[buf];
    int row  = blockIdx.x * 8 + (threadIdx.x >> 5);
    int lane = threadIdx.x & 31;
    constexpr int V = N / 128;   // float4 per lane
    float* rp = data + (size_t)row * N;
    float4 v[V];
    float s = 0.0f, s2 = 0.0f;
#pragma unroll
    for (int i = 0; i < V; i++) {
        v[i] = *(const float4*)(rp + (i * 32 + lane) * 4);
        s  += v[i].x + v[i].y + v[i].z + v[i].w;
        s2 += v[i].x * v[i].x + v[i].y * v[i].y + v[i].z * v[i].z + v[i].w * v[i].w;
    }
#pragma unroll
    for (int o = 16; o > 0; o >>= 1) {
        s  += __shfl_xor_sync(0xFFFFFFFFu, s,  o);
        s2 += __shfl_xor_sync(0xFFFFFFFFu, s2, o);
    }
    float mu  = s * (1.0f / N);
    float var = s2 * (1.0f / N) - mu * mu;
    float inv = rsqrtf(var + 1e-5f);
#pragma unroll
    for (int i = 0; i < V; i++) {
        int c = (i * 32 + lane) * 4;
        float4 gg = *(const float4*)(g + c);
        float4 bb = *(const float4*)(be + c);
        float4 o;
        o.x = (v[i].x - mu) * inv * gg.x + bb.x;
        o.y = (v[i].y - mu) * inv * gg.y + bb.y;
        o.z = (v[i].z - mu) * inv * gg.z + bb.z;
        o.w = (v[i].w - mu) * inv * gg.w + bb.w;
        *(float4*)(rp + c) = o;
    }
}

// ---------------- K1: encoder Linear(8->256) + GELU + LayerNorm --------------
__global__ __launch_bounds__(256) void k_encoder(
    const float* __restrict__ x, const float* __restrict__ W,
    const float* __restrict__ b, const float* __restrict__ g,
    const float* __restrict__ be)
{
    __shared__ float xs[8];
    __shared__ float red[256];
    int row = blockIdx.x, t = threadIdx.x;
    if (t < 8) xs[t] = x[row * 8 + t];
    __syncthreads();
    float acc = b[t];
#pragma unroll
    for (int k = 0; k < 8; k++) acc = fmaf(xs[k], W[k * NH0 + t], acc);
    float v = geluf(acc);
    float mu  = block_reduce_sum(v, red, 256) * (1.0f / NH0);
    float d   = v - mu;
    float var = block_reduce_sum(d * d, red, 256) * (1.0f / NH0);
    g_h0[(size_t)row * NH0 + t] = d * rsqrtf(var + 1e-5f) * g[t] + be[t];
}

// ---------------- K4: flux GEMM via tf32 mma + cummax epilogue ---------------
// flux = sigmoid(tanh(cummax(z)))  (monotone fns commute with cummax)
__global__ __launch_bounds__(256) void k_final_mma(
    int src, const float* __restrict__ W,
    const float* __restrict__ bias, float* __restrict__ flux,
    size_t out_elems)
{
    const float* A = g_ptrs[src];
    __shared__ union {
        MMASmem mm;
        float zs[128][65];
    } sm;

    int tid = threadIdx.x, wid = tid >> 5, lane = tid & 31;
    int group = lane >> 2, tg = lane & 3;
    int wm = (wid >> 1) * 32, wn = (wid & 1) * 32;
    int m0 = blockIdx.y * 128;
    int n0 = blockIdx.x * 64;   // one 64-col grid row

    float d[2][4][4] = {};
    mma_tiles<NH2, NF>(A, W, m0, n0, sm.mm, d, wm, wn, group, tg, tid);

    // z (+bias) into zs (smem reuse)
#pragma unroll
    for (int mt = 0; mt < 2; mt++) {
#pragma unroll
        for (int nt = 0; nt < 4; nt++) {
            int rb = wm + mt * 16 + group;
            int cb = wn + nt * 8 + 2 * tg;
            float bz0 = bias[n0 + cb], bz1 = bias[n0 + cb + 1];
            sm.zs[rb    ][cb    ] = d[mt][nt][0] + bz0;
            sm.zs[rb    ][cb + 1] = d[mt][nt][1] + bz1;
            sm.zs[rb + 8][cb    ] = d[mt][nt][2] + bz0;
            sm.zs[rb + 8][cb + 1] = d[mt][nt][3] + bz1;
        }
    }
    __syncthreads();

    if (tid < 128) {   // inclusive running max along the 64-col row
        float run = -3.402823466e38f;
#pragma unroll 4
        for (int j = 0; j < 64; j++) {
            run = fmaxf(run, sm.zs[tid][j]);
            sm.zs[tid][j] = run;
        }
    }
    __syncthreads();

#pragma unroll
    for (int i = 0; i < 32; i++) {
        int idx = tid + 256 * i;
        int r = idx >> 6, c = idx & 63;
        float z = sm.zs[r][c];
        float e2z = __expf(2.0f * z);
        float th  = (e2z - 1.0f) / (e2z + 1.0f);
        float f   = 1.0f / (1.0f + __expf(-th));
        size_t gi = (size_t)(m0 + r) * NF + n0 + c;
        if (gi < out_elems) flux[gi] = f;
    }
}

// ---------------- K5: per-sample physics -------------------------------------
__global__ __launch_bounds__(256) void k_physics(
    const float* __restrict__ flux, const float* __restrict__ x,
    float* __restrict__ out, size_t out_elems)
{
    __shared__ float fs[64][65];
    __shared__ float red[256];
    int b = blockIdx.x, t = threadIdx.x;
    const float* fb = flux + (size_t)b * NF;
    float lsum = 0.0f;
#pragma unroll
    for (int i = 0; i < 16; i++) {
        int idx = i * 256 + t;
        float v = fb[idx];
        fs[idx >> 6][idx & 63] = v;
        lsum += v;
    }
    __syncthreads();
    float S  = block_reduce_sum(lsum, red, 256);
    float x0 = x[(size_t)b * 8];
    float lq = 0.0f;
    for (int p = t; p < 62 * 62; p += 256) {
        int i = p / 62 + 1, j = p % 62 + 1;
        float lap = fs[i + 1][j] + fs[i - 1][j] + fs[i][j + 1] + fs[i][j - 1]
                    - 4.0f * fs[i][j];
        float dd = lap - x0;
        lq = fmaf(dd, dd, lq);
    }
    float LQ = block_reduce_sum(lq, red, 256);
    if (t == 0) {
        g_gs[b] = LQ + 252.0f * x0 * x0;
        float dc = x0 - S;
        g_cc[b] = dc * dc;
        size_t pi = OFF_P + (size_t)b;
        if (pi < out_elems) out[pi] = expf(-2.0f * S * (1.0f / NF));
    }
    if (t < 64) {
        size_t qi = OFF_Q + (size_t)b * G + t;
        if (qi < out_elems) out[qi] = 0.8f + (float)t * (2.7f / 63.0f);
    }
}

// ---------------- K6: scalar loss --------------------------------------------
__global__ __launch_bounds__(1024) void k_loss(const float* __restrict__ pw,
                                               float* __restrict__ out,
                                               size_t out_elems)
{
    __shared__ float r1[1024];
    __shared__ float r2[1024];
    int t = threadIdx.x;
    float sg = 0.0f, sc = 0.0f;
    for (int i = t; i < BATCH; i += 1024) { sg += g_gs[i]; sc += g_cc[i]; }
    r1[t] = sg; r2[t] = sc;
    __syncthreads();
    for (int s = 512; s > 0; s >>= 1) {
        if (t < s) { r1[t] += r1[t + s]; r2[t] += r2[t + s]; }
        __syncthreads();
    }
    if (t == 0 && OFF_LOSS < out_elems) {
        float gs_res = r1[0] * (1.0f / ((float)BATCH * (float)NF));
        float cc     = r2[0] * (1.0f / (float)BATCH);
        float stab   = fmaxf(0.0f, 1.1f - 0.8f);
        out[OFF_LOSS] = pw[0] * gs_res + pw[1] * cc + pw[2] * stab;
    }
}

// ---------------- launch -----------------------------------------------------
extern "C" void kernel_launch(void* const* d_in, const int* in_sizes, int n_in,
                              void* d_out, int out_size)
{
    (void)in_sizes; (void)n_in;
    const float* x     = (const float*)d_in[0];
    const float* Wenc  = (const float*)d_in[1];
    const float* benc  = (const float*)d_in[2];
    const float* genc  = (const float*)d_in[3];
    const float* beenc = (const float*)d_in[4];
    const float* W1    = (const float*)d_in[5];
    const float* b1    = (const float*)d_in[6];
    const float* g1    = (const float*)d_in[7];
    const float* be1   = (const float*)d_in[8];
    const float* W2    = (const float*)d_in[9];
    const float* b2    = (const float*)d_in[10];
    const float* g2    = (const float*)d_in[11];
    const float* be2   = (const float*)d_in[12];
    const float* Wf    = (const float*)d_in[13];
    const float* bf    = (const float*)d_in[14];
    const float* pw    = (const float*)d_in[15];

    float* out = (float*)d_out;
    size_t out_elems = (size_t)out_size;

    k_init_ptrs<<<1, 1>>>();
    k_encoder<<<BATCH, 256>>>(x, Wenc, benc, genc, beenc);
    k_gemm_tf32<NH0, NH1><<<dim3(NH1 / 64, BATCH / 128), 256>>>(0, W1, b1, 1);
    k_layernorm_warp<NH1><<<BATCH / 8, 256>>>(1, g1, be1);
    k_gemm_tf32<NH1, NH2><<<dim3(NH2 / 64, BATCH / 128), 256>>>(1, W2, b2, 2);
    k_layernorm_warp<NH2><<<BATCH / 8, 256>>>(2, g2, be2);
    k_final_mma<<<dim3(NF / 64, BATCH / 128), 256>>>(2, Wf, bf, out, out_elems);
    k_physics<<<BATCH, 256>>>(out, x, out, out_elems);
    k_loss<<<1, 1024>>>(pw, out, out_elems);
}

// round 7
// speedup vs baseline: 2.2323x; 1.2207x over previous
#include <cuda_runtime.h>
#include <math.h>
#include <stdint.h>

#define BATCH 16384
#define G 64
#define NH0 256
#define NH1 512
#define NH2 256
#define NF 4096   // G*G

// packed fp32 output: flux [B,64,64] | q [B,64] | pressure [B] | loss [1]
#define OFF_Q    ((size_t)BATCH * NF)
#define OFF_P    (OFF_Q + (size_t)BATCH * G)
#define OFF_LOSS (OFF_P + (size_t)BATCH)

// ---------------- scratch ----------------------------------------------------
__device__ float g_h0[(size_t)BATCH * NH0];
__device__ float g_t1[(size_t)BATCH * NH1];
__device__ float g_t2[(size_t)BATCH * NH2];
__device__ float g_gs[BATCH];
__device__ float g_cc[BATCH];

__device__ float* g_ptrs[3];
__global__ void k_init_ptrs() {
    g_ptrs[0] = g_h0; g_ptrs[1] = g_t1; g_ptrs[2] = g_t2;
}

// ---------------- helpers ----------------------------------------------------
__device__ __forceinline__ float geluf(float x) {
    return 0.5f * x * (1.0f + erff(x * 0.70710678118654752440f));
}

// block-wide sum for 256 threads: warp shuffles + 8-slot smem (2 barriers)
__device__ __forceinline__ float block_sum_256(float v, float* w8) {
    int lane = threadIdx.x & 31, wid = threadIdx.x >> 5;
#pragma unroll
    for (int o = 16; o > 0; o >>= 1) v += __shfl_xor_sync(0xFFFFFFFFu, v, o);
    if (lane == 0) w8[wid] = v;
    __syncthreads();
    float s = 0.0f;
#pragma unroll
    for (int i = 0; i < 8; i++) s += w8[i];
    __syncthreads();
    return s;
}

__device__ __forceinline__ uint32_t f2tf32(float f) {
    uint32_t u;
    asm("cvt.rna.tf32.f32 %0, %1;" : "=r"(u) : "f"(f));
    return u;
}

__device__ __forceinline__ uint4 cvt4(float4 v) {
    return make_uint4(f2tf32(v.x), f2tf32(v.y), f2tf32(v.z), f2tf32(v.w));
}

__device__ __forceinline__ void mma_tf32(float d[4],
    uint32_t a0, uint32_t a1, uint32_t a2, uint32_t a3,
    uint32_t b0, uint32_t b1)
{
    asm volatile(
        "mma.sync.aligned.m16n8k8.row.col.f32.tf32.tf32.f32 "
        "{%0,%1,%2,%3}, {%4,%5,%6,%7}, {%8,%9}, {%0,%1,%2,%3};\n"
        : "+f"(d[0]), "+f"(d[1]), "+f"(d[2]), "+f"(d[3])
        : "r"(a0), "r"(a1), "r"(a2), "r"(a3), "r"(b0), "r"(b1));
}

// ---------------- shared tf32 GEMM mainloop (register-pipelined) -------------
// block tile 128(M) x 64(N), 8 warps 4(m)x2(n), warp 32x32, K chunked by 32.
// smem holds PRE-CONVERTED tf32; next chunk prefetched to regs during compute.
#define AS_STRIDE 36
#define BS_STRIDE 72

struct MMASmem {
    uint32_t As[128][AS_STRIDE];   // [m][k] chunk, tf32 bits
    uint32_t Bs[32][BS_STRIDE];    // [k][n] chunk, tf32 bits
};

template <int K, int NSTR>
__device__ __forceinline__ void mma_tiles(
    const float* __restrict__ A, const float* __restrict__ W,
    int m0, int n0, MMASmem& sm, float (&d)[2][4][4],
    int wm, int wn, int group, int tg, int tid)
{
    const float* Ag = A + (size_t)m0 * K;
    const float* Wg = W + n0;
    const int arow = tid >> 3, acol = (tid & 7) * 4;    // + 32*it rows
    const int brow = tid >> 4, bcol = (tid & 15) * 4;   // + 16*it rows

    float4 ra[4], rb[2];
#pragma unroll
    for (int it = 0; it < 4; it++)
        ra[it] = *(const float4*)(Ag + (size_t)(arow + 32 * it) * K + acol);
#pragma unroll
    for (int it = 0; it < 2; it++)
        rb[it] = *(const float4*)(Wg + (size_t)(brow + 16 * it) * NSTR + bcol);

#pragma unroll 1
    for (int k0 = 0; k0 < K; k0 += 32) {
        // commit prefetched chunk to smem (cvt to tf32)
#pragma unroll
        for (int it = 0; it < 4; it++)
            *(uint4*)&sm.As[arow + 32 * it][acol] = cvt4(ra[it]);
#pragma unroll
        for (int it = 0; it < 2; it++)
            *(uint4*)&sm.Bs[brow + 16 * it][bcol] = cvt4(rb[it]);
        __syncthreads();

        // prefetch next chunk (latency overlapped with MMA compute below)
        if (k0 + 32 < K) {
#pragma unroll
            for (int it = 0; it < 4; it++)
                ra[it] = *(const float4*)(Ag + (size_t)(arow + 32 * it) * K
                                          + (k0 + 32) + acol);
#pragma unroll
            for (int it = 0; it < 2; it++)
                rb[it] = *(const float4*)(Wg + (size_t)(k0 + 32 + brow + 16 * it) * NSTR
                                          + bcol);
        }

#pragma unroll
        for (int ks = 0; ks < 32; ks += 8) {
            uint32_t afr[2][4];
#pragma unroll
            for (int mt = 0; mt < 2; mt++) {
                int mb = wm + mt * 16;
                afr[mt][0] = sm.As[mb + group    ][ks + tg    ];
                afr[mt][1] = sm.As[mb + group + 8][ks + tg    ];
                afr[mt][2] = sm.As[mb + group    ][ks + tg + 4];
                afr[mt][3] = sm.As[mb + group + 8][ks + tg + 4];
            }
            uint32_t bfr[4][2];
#pragma unroll
            for (int nt = 0; nt < 4; nt++) {
                int nb = wn + nt * 8;
                bfr[nt][0] = sm.Bs[ks + tg    ][nb + group];
                bfr[nt][1] = sm.Bs[ks + tg + 4][nb + group];
            }
#pragma unroll
            for (int mt = 0; mt < 2; mt++)
#pragma unroll
                for (int nt = 0; nt < 4; nt++)
                    mma_tf32(d[mt][nt],
                             afr[mt][0], afr[mt][1], afr[mt][2], afr[mt][3],
                             bfr[nt][0], bfr[nt][1]);
        }
        __syncthreads();
    }
}

// ---------------- hidden GEMM: tf32 mma + bias + GELU ------------------------
template <int K, int NOUT>
__global__ __launch_bounds__(256) void k_gemm_tf32(
    int src, const float* __restrict__ W,
    const float* __restrict__ bias, int dst)
{
    const float* A = g_ptrs[src];
    float* C = g_ptrs[dst];
    __shared__ MMASmem sm;
    int tid = threadIdx.x, wid = tid >> 5, lane = tid & 31;
    int group = lane >> 2, tg = lane & 3;
    int wm = (wid >> 1) * 32, wn = (wid & 1) * 32;
    int m0 = blockIdx.y * 128, n0 = blockIdx.x * 64;
    float d[2][4][4] = {};
    mma_tiles<K, NOUT>(A, W, m0, n0, sm, d, wm, wn, group, tg, tid);
#pragma unroll
    for (int mt = 0; mt < 2; mt++) {
#pragma unroll
        for (int nt = 0; nt < 4; nt++) {
            int r0 = m0 + wm + mt * 16 + group;
            int c  = n0 + wn + nt * 8 + 2 * tg;
            float b0 = bias[c], b1 = bias[c + 1];
            float2 o0 = make_float2(geluf(d[mt][nt][0] + b0), geluf(d[mt][nt][1] + b1));
            float2 o1 = make_float2(geluf(d[mt][nt][2] + b0), geluf(d[mt][nt][3] + b1));
            *(float2*)&C[(size_t)r0 * NOUT + c]       = o0;
            *(float2*)&C[(size_t)(r0 + 8) * NOUT + c] = o1;
        }
    }
}

// ---------------- warp-per-row LayerNorm -------------------------------------
template <int N>
__global__ __launch_bounds__(256) void k_layernorm_warp(
    int buf, const float* __restrict__ g, const float* __restrict__ be)
{
    float* data = g_ptrs[buf];
    int row  = blockIdx.x * 8 + (threadIdx.x >> 5);
    int lane = threadIdx.x & 31;
    constexpr int V = N / 128;
    float* rp = data + (size_t)row * N;
    float4 v[V];
    float s = 0.0f, s2 = 0.0f;
#pragma unroll
    for (int i = 0; i < V; i++) {
        v[i] = *(const float4*)(rp + (i * 32 + lane) * 4);
        s  += v[i].x + v[i].y + v[i].z + v[i].w;
        s2 += v[i].x * v[i].x + v[i].y * v[i].y + v[i].z * v[i].z + v[i].w * v[i].w;
    }
#pragma unroll
    for (int o = 16; o > 0; o >>= 1) {
        s  += __shfl_xor_sync(0xFFFFFFFFu, s,  o);
        s2 += __shfl_xor_sync(0xFFFFFFFFu, s2, o);
    }
    float mu  = s * (1.0f / N);
    float var = s2 * (1.0f / N) - mu * mu;
    float inv = rsqrtf(var + 1e-5f);
#pragma unroll
    for (int i = 0; i < V; i++) {
        int c = (i * 32 + lane) * 4;
        float4 gg = *(const float4*)(g + c);
        float4 bb = *(const float4*)(be + c);
        float4 o;
        o.x = (v[i].x - mu) * inv * gg.x + bb.x;
        o.y = (v[i].y - mu) * inv * gg.y + bb.y;
        o.z = (v[i].z - mu) * inv * gg.z + bb.z;
        o.w = (v[i].w - mu) * inv * gg.w + bb.w;
        *(float4*)(rp + c) = o;
    }
}

// ---------------- K1: encoder Linear(8->256) + GELU + LayerNorm --------------
__global__ __launch_bounds__(256) void k_encoder(
    const float* __restrict__ x, const float* __restrict__ W,
    const float* __restrict__ b, const float* __restrict__ g,
    const float* __restrict__ be)
{
    __shared__ float xs[8];
    __shared__ float w8[8];
    int row = blockIdx.x, t = threadIdx.x;
    if (t < 8) xs[t] = x[row * 8 + t];
    __syncthreads();
    float acc = b[t];
#pragma unroll
    for (int k = 0; k < 8; k++) acc = fmaf(xs[k], W[k * NH0 + t], acc);
    float v = geluf(acc);
    float mu  = block_sum_256(v, w8) * (1.0f / NH0);
    float d   = v - mu;
    float var = block_sum_256(d * d, w8) * (1.0f / NH0);
    g_h0[(size_t)row * NH0 + t] = d * rsqrtf(var + 1e-5f) * g[t] + be[t];
}

// ---------------- K4: flux GEMM via tf32 mma + cummax epilogue ---------------
// flux = sigmoid(tanh(cummax(z)))  (monotone fns commute with cummax)
// NOTE: zs stride 68 (multiple of 4) so float4 epilogue loads are 16B-aligned.
#define ZS_STRIDE 68

__global__ __launch_bounds__(256) void k_final_mma(
    int src, const float* __restrict__ W,
    const float* __restrict__ bias, float* __restrict__ flux,
    size_t out_elems)
{
    const float* A = g_ptrs[src];
    __shared__ union {
        MMASmem mm;
        float zs[128][ZS_STRIDE];
    } sm;

    int tid = threadIdx.x, wid = tid >> 5, lane = tid & 31;
    int group = lane >> 2, tg = lane & 3;
    int wm = (wid >> 1) * 32, wn = (wid & 1) * 32;
    int m0 = blockIdx.y * 128;
    int n0 = blockIdx.x * 64;   // one 64-col grid row

    float d[2][4][4] = {};
    mma_tiles<NH2, NF>(A, W, m0, n0, sm.mm, d, wm, wn, group, tg, tid);

#pragma unroll
    for (int mt = 0; mt < 2; mt++) {
#pragma unroll
        for (int nt = 0; nt < 4; nt++) {
            int rb = wm + mt * 16 + group;
            int cb = wn + nt * 8 + 2 * tg;
            float bz0 = bias[n0 + cb], bz1 = bias[n0 + cb + 1];
            sm.zs[rb    ][cb    ] = d[mt][nt][0] + bz0;
            sm.zs[rb    ][cb + 1] = d[mt][nt][1] + bz1;
            sm.zs[rb + 8][cb    ] = d[mt][nt][2] + bz0;
            sm.zs[rb + 8][cb + 1] = d[mt][nt][3] + bz1;
        }
    }
    __syncthreads();

    if (tid < 128) {   // inclusive running max along the 64-col row
        float run = -3.402823466e38f;
#pragma unroll 4
        for (int j = 0; j < 64; j++) {
            run = fmaxf(run, sm.zs[tid][j]);
            sm.zs[tid][j] = run;
        }
    }
    __syncthreads();

    // vectorized transcendental epilogue + float4 store
#pragma unroll
    for (int i = 0; i < 8; i++) {
        int idx4 = tid + 256 * i;          // float4 index in 128x64 tile
        int r = idx4 >> 4, c = (idx4 & 15) * 4;
        float4 z = *(const float4*)&sm.zs[r][c];
        float4 f;
        {
            float e = __expf(2.0f * z.x); float th = (e - 1.0f) / (e + 1.0f);
            f.x = 1.0f / (1.0f + __expf(-th));
            e = __expf(2.0f * z.y); th = (e - 1.0f) / (e + 1.0f);
            f.y = 1.0f / (1.0f + __expf(-th));
            e = __expf(2.0f * z.z); th = (e - 1.0f) / (e + 1.0f);
            f.z = 1.0f / (1.0f + __expf(-th));
            e = __expf(2.0f * z.w); th = (e - 1.0f) / (e + 1.0f);
            f.w = 1.0f / (1.0f + __expf(-th));
        }
        size_t gi = (size_t)(m0 + r) * NF + n0 + c;
        if (gi + 3 < out_elems) *(float4*)&flux[gi] = f;
    }
}

// ---------------- K5: per-sample physics -------------------------------------
__global__ __launch_bounds__(256) void k_physics(
    const float* __restrict__ flux, const float* __restrict__ x,
    float* __restrict__ out, size_t out_elems)
{
    __shared__ float fs[64][68];
    __shared__ float wsum[8], wq[8];
    int b = blockIdx.x, t = threadIdx.x;
    int lane = t & 31, wid = t >> 5;
    const float4* fb4 = (const float4*)(flux + (size_t)b * NF);
    float lsum = 0.0f;
#pragma unroll
    for (int i = 0; i < 4; i++) {
        int idx4 = t + 256 * i;                  // 0..1023
        float4 v = fb4[idx4];
        int r = idx4 >> 4, c = (idx4 & 15) * 4;
        *(float4*)&fs[r][c] = v;
        lsum += v.x + v.y + v.z + v.w;
    }
#pragma unroll
    for (int o = 16; o > 0; o >>= 1) lsum += __shfl_xor_sync(0xFFFFFFFFu, lsum, o);
    if (lane == 0) wsum[wid] = lsum;
    __syncthreads();

    float x0 = __ldg(x + (size_t)b * 8);
    float lq = 0.0f;
    if (t < 248) {                                // div/mod-free interior sweep
        int r  = (t >> 2) + 1;                    // 1..62
        int j0 = (t & 3) * 16 + 1;                // 1,17,33,49
#pragma unroll
        for (int jj = 0; jj < 16; jj++) {
            int j = j0 + jj;
            if (j <= 62) {
                float lap = fs[r + 1][j] + fs[r - 1][j] + fs[r][j + 1]
                          + fs[r][j - 1] - 4.0f * fs[r][j];
                float dd = lap - x0;
                lq = fmaf(dd, dd, lq);
            }
        }
    }
#pragma unroll
    for (int o = 16; o > 0; o >>= 1) lq += __shfl_xor_sync(0xFFFFFFFFu, lq, o);
    if (lane == 0) wq[wid] = lq;
    __syncthreads();

    if (t == 0) {
        float S = 0.0f, LQ = 0.0f;
#pragma unroll
        for (int i = 0; i < 8; i++) { S += wsum[i]; LQ += wq[i]; }
        g_gs[b] = LQ + 252.0f * x0 * x0;          // boundary: lap=0 -> x0^2
        float dc = x0 - S;
        g_cc[b] = dc * dc;
        size_t pi = OFF_P + (size_t)b;
        if (pi < out_elems) out[pi] = expf(-2.0f * S * (1.0f / NF));
    }
    if (t < 64) {
        size_t qi = OFF_Q + (size_t)b * G + t;
        if (qi < out_elems) out[qi] = 0.8f + (float)t * (2.7f / 63.0f);
    }
}

// ---------------- K6: scalar loss --------------------------------------------
__global__ __launch_bounds__(1024) void k_loss(const float* __restrict__ pw,
                                               float* __restrict__ out,
                                               size_t out_elems)
{
    __shared__ float r1[1024];
    __shared__ float r2[1024];
    int t = threadIdx.x;
    float sg = 0.0f, sc = 0.0f;
    for (int i = t; i < BATCH; i += 1024) { sg += g_gs[i]; sc += g_cc[i]; }
    r1[t] = sg; r2[t] = sc;
    __syncthreads();
    for (int s = 512; s > 0; s >>= 1) {
        if (t < s) { r1[t] += r1[t + s]; r2[t] += r2[t + s]; }
        __syncthreads();
    }
    if (t == 0 && OFF_LOSS < out_elems) {
        float gs_res = r1[0] * (1.0f / ((float)BATCH * (float)NF));
        float cc     = r2[0] * (1.0f / (float)BATCH);
        float stab   = fmaxf(0.0f, 1.1f - 0.8f);
        out[OFF_LOSS] = pw[0] * gs_res + pw[1] * cc + pw[2] * stab;
    }
}

// ---------------- launch -----------------------------------------------------
extern "C" void kernel_launch(void* const* d_in, const int* in_sizes, int n_in,
                              void* d_out, int out_size)
{
    (void)in_sizes; (void)n_in;
    const float* x     = (const float*)d_in[0];
    const float* Wenc  = (const float*)d_in[1];
    const float* benc  = (const float*)d_in[2];
    const float* genc  = (const float*)d_in[3];
    const float* beenc = (const float*)d_in[4];
    const float* W1    = (const float*)d_in[5];
    const float* b1    = (const float*)d_in[6];
    const float* g1    = (const float*)d_in[7];
    const float* be1   = (const float*)d_in[8];
    const float* W2    = (const float*)d_in[9];
    const float* b2    = (const float*)d_in[10];
    const float* g2    = (const float*)d_in[11];
    const float* be2   = (const float*)d_in[12];
    const float* Wf    = (const float*)d_in[13];
    const float* bf    = (const float*)d_in[14];
    const float* pw    = (const float*)d_in[15];

    float* out = (float*)d_out;
    size_t out_elems = (size_t)out_size;

    k_init_ptrs<<<1, 1>>>();
    k_encoder<<<BATCH, 256>>>(x, Wenc, benc, genc, beenc);
    k_gemm_tf32<NH0, NH1><<<dim3(NH1 / 64, BATCH / 128), 256>>>(0, W1, b1, 1);
    k_layernorm_warp<NH1><<<BATCH / 8, 256>>>(1, g1, be1);
    k_gemm_tf32<NH1, NH2><<<dim3(NH2 / 64, BATCH / 128), 256>>>(1, W2, b2, 2);
    k_layernorm_warp<NH2><<<BATCH / 8, 256>>>(2, g2, be2);
    k_final_mma<<<dim3(NF / 64, BATCH / 128), 256>>>(2, Wf, bf, out, out_elems);
    k_physics<<<BATCH, 256>>>(out, x, out, out_elems);
    k_loss<<<1, 1024>>>(pw, out, out_elems);
}